// round 15
// baseline (speedup 1.0000x reference)
#include <cuda_runtime.h>
#include <math.h>
#include <stdint.h>

// Problem constants
#define Bb   8
#define Dd   49
#define Cch  512
#define Nn   12
#define Hh   256          // C/2
#define Ee   144          // N*N
#define ND   392          // B*D
#define RQ   4704         // N*B*D
#define SQ   588          // N*D (rows per batch in attn2)
#define SCALE_ 0.0625f    // (C/2)^-0.5
#define EPS_  1e-5f

#define GEMM_SMEM 81920   // 4 stages * (A 10240B + B 10240B), BK=16

// ---------------- static device scratch (zero-initialized at load) ----------
__device__ float g_h[RQ * Cch];
__device__ float g_q1[RQ * Hh];
__device__ float g_k1[ND * Hh];
__device__ float g_v1[(ND + 16) * Cch];  // padded rows stay 0 (zero-init)
__device__ float g_S1[96 * Dd * Dd];
__device__ float g_P[96 * Dd * 64];
__device__ float g_feat1[RQ * Cch];      // rows (b*12+n)*49+d  (b-major)
__device__ float g_QK2[RQ * Cch];        // cols 0-255 = Q2, 256-511 = K2
__device__ float g_Vp[RQ * Cch];
__device__ float g_Wvp[Cch * Cch];
__device__ float g_bvp[Cch];
__device__ float g_wqk[Cch * Cch];
__device__ float g_bqk[Cch];
__device__ float g_S[Bb * SQ * SQ];
__device__ float g_MV[Bb * Nn * Dd * Dd];
__device__ float g_w[Bb * Ee * Dd];
__device__ float g_gram[Bb * Ee];
__device__ float g_fv[Bb * Nn * Cch];
__device__ float g_zbar[Bb * Ee * Cch];
__device__ float g_ps1[Bb * Ee];
__device__ float g_ps2[Bb * Ee];
__device__ float g_bn1m[Nn * Cch];
__device__ float g_bn1r[Nn * Cch];
__device__ float g_mask[Bb * Ee];
__device__ float g_fe[Bb * Ee * Cch];
__device__ float g_wnodeA[Cch * 2048];
__device__ float g_wnodeB[Cch * 2048];
__device__ float g_xnode[Bb * Nn * 2048];
__device__ float g_xw[Bb * Ee * Cch];
__device__ float g_msg[Bb * Nn * Cch];

// ---------------- helpers ----------------------------------------------------
__device__ __forceinline__ float block_reduce_sum(float v, float* sm) {
    int lane = threadIdx.x & 31, w = threadIdx.x >> 5;
#pragma unroll
    for (int o = 16; o; o >>= 1) v += __shfl_xor_sync(0xffffffffu, v, o);
    if (lane == 0) sm[w] = v;
    __syncthreads();
    int nw = (blockDim.x + 31) >> 5;
    float r = 0.f;
    if (threadIdx.x < 32) {
        r = (threadIdx.x < nw) ? sm[threadIdx.x] : 0.f;
#pragma unroll
        for (int o = 16; o; o >>= 1) r += __shfl_xor_sync(0xffffffffu, r, o);
        if (threadIdx.x == 0) sm[0] = r;
    }
    __syncthreads();
    r = sm[0];
    __syncthreads();
    return r;
}

__device__ __forceinline__ void mma_tf32(float* c, const uint32_t* a, const uint32_t* b) {
    asm volatile(
        "mma.sync.aligned.m16n8k8.row.col.f32.tf32.tf32.f32 "
        "{%0,%1,%2,%3}, {%4,%5,%6,%7}, {%8,%9}, {%0,%1,%2,%3};"
        : "+f"(c[0]), "+f"(c[1]), "+f"(c[2]), "+f"(c[3])
        : "r"(a[0]), "r"(a[1]), "r"(a[2]), "r"(a[3]), "r"(b[0]), "r"(b[1]));
}

__device__ __forceinline__ void cp16(uint32_t s, const void* g, int sz) {
    asm volatile("cp.async.ca.shared.global [%0], [%1], 16, %2;"
                 :: "r"(s), "l"(g), "r"(sz));
}

__device__ __forceinline__ float4 f4add(float4 a, float4 b) {
    return make_float4(a.x + b.x, a.y + b.y, a.z + b.z, a.w + b.w);
}

// ---------------- gemm_tc: TF32 TC GEMM, 128x128x16, 4-stage cp.async --------
// 512 threads / 16 warps (4x4 warp grid, 32x32 per warp) for latency hiding.
// Smem fp32: A[m][k] stride 20, B NN [k][n] stride 136, B NT [n][k] stride 20.
// One commit_group per k-tile; wait_group 2 (depth-3 prefetch); 1 sync/tile.
// MMA consumes raw fp32 bits as tf32 (mantissa truncation) — no cvt in loop.
// OOB rows/cols: predicate src-size=0 with pointer clamped in-bounds.
__global__ __launch_bounds__(512, 1) void gemm_tc(
    const float* __restrict__ A, const float* __restrict__ Bm,
    const float* __restrict__ bias, float* __restrict__ Cm,
    int M, int Np, int K, int lda, int ldb, int ldc,
    long sA1, long sA2, long sB1, long sB2, long sC1, long sC2,
    int zdiv, int transB)
{
    const int S = 4;
    extern __shared__ float smem[];
    float* Asm = smem;              // [S][2560]  A: m*20+k
    float* Bsm = smem + S * 2560;   // [S][2560]  B: NN k*136+n / NT n*20+k

    int z = blockIdx.z;
    int zq = z / zdiv, zr = z % zdiv;
    const float* Az = A + zq * sA1 + (long)zr * sA2;
    const float* Bz = Bm + zq * sB1 + (long)zr * sB2;
    float* Cz = Cm + zq * sC1 + (long)zr * sC2;

    int tid = threadIdx.x;
    int row0 = blockIdx.y * 128, col0 = blockIdx.x * 128;
    int warp = tid >> 5, lane = tid & 31;
    int wm = (warp & 3) * 32, wn = (warp >> 2) * 32;
    int gid = lane >> 2, tig = lane & 3;

    float c[2][4][4];
#pragma unroll
    for (int mi = 0; mi < 2; mi++)
#pragma unroll
        for (int ni = 0; ni < 4; ni++)
#pragma unroll
            for (int q = 0; q < 4; q++) c[mi][ni][q] = 0.f;

    int nt = K >> 4;

#define ISSUE(t)                                                               \
    {                                                                          \
        int k0_ = (t) << 4;                                                    \
        float* Ab_ = Asm + ((t) % S) * 2560;                                   \
        float* Bb_ = Bsm + ((t) % S) * 2560;                                   \
        {                                                                      \
            int row_ = tid >> 2, kq_ = (tid & 3) * 4;                          \
            int gr_ = row0 + row_;                                             \
            int ok_ = (gr_ < M);                                               \
            const float* gp_ = Az + (long)(ok_ ? gr_ : 0) * lda + k0_ + kq_;   \
            uint32_t sa_ = (uint32_t)__cvta_generic_to_shared(                 \
                Ab_ + row_ * 20 + kq_);                                        \
            cp16(sa_, gp_, ok_ ? 16 : 0);                                      \
        }                                                                      \
        if (!transB) {                                                         \
            int kk_ = tid >> 5, n4_ = (tid & 31) * 4;                          \
            int gc_ = col0 + n4_;                                              \
            int ok_ = (gc_ < Np);                                              \
            const float* gp_ = Bz + (long)(k0_ + kk_) * ldb +                  \
                               (ok_ ? gc_ : 0);                                \
            uint32_t sa_ = (uint32_t)__cvta_generic_to_shared(                 \
                Bb_ + kk_ * 136 + n4_);                                        \
            cp16(sa_, gp_, ok_ ? 16 : 0);                                      \
        } else {                                                               \
            int row_ = tid >> 2, kq_ = (tid & 3) * 4;                          \
            int gn_ = col0 + row_;                                             \
            int ok_ = (gn_ < Np);                                              \
            const float* gp_ = Bz + (long)(ok_ ? gn_ : 0) * ldb +              \
                               k0_ + kq_;                                      \
            uint32_t sa_ = (uint32_t)__cvta_generic_to_shared(                 \
                Bb_ + row_ * 20 + kq_);                                        \
            cp16(sa_, gp_, ok_ ? 16 : 0);                                      \
        }                                                                      \
        asm volatile("cp.async.commit_group;");                                \
    }

    // preload S-1 stages (empty commits keep group counts consistent)
#pragma unroll
    for (int pt = 0; pt < S - 1; pt++) {
        if (pt < nt) ISSUE(pt)
        else asm volatile("cp.async.commit_group;");
    }

    for (int t = 0; t < nt; t++) {
        asm volatile("cp.async.wait_group 2;");  // stage t complete
        __syncthreads();                          // visible; prior compute done
        if (t + S - 1 < nt) ISSUE(t + S - 1)
        else asm volatile("cp.async.commit_group;");

        const float* Apt = Asm + (t % S) * 2560;
        const float* Bpt = Bsm + (t % S) * 2560;
#pragma unroll
        for (int k8i = 0; k8i < 2; k8i++) {
            int kk = k8i * 8 + tig;
            uint32_t af[2][4], bf[4][2];
#pragma unroll
            for (int mi = 0; mi < 2; mi++) {
                int mb = wm + mi * 16 + gid;
                af[mi][0] = __float_as_uint(Apt[mb * 20 + kk]);
                af[mi][2] = __float_as_uint(Apt[mb * 20 + kk + 4]);
                af[mi][1] = __float_as_uint(Apt[(mb + 8) * 20 + kk]);
                af[mi][3] = __float_as_uint(Apt[(mb + 8) * 20 + kk + 4]);
            }
            if (!transB) {
#pragma unroll
                for (int ni = 0; ni < 4; ni++) {
                    int nb = wn + ni * 8 + gid;
                    bf[ni][0] = __float_as_uint(Bpt[kk * 136 + nb]);
                    bf[ni][1] = __float_as_uint(Bpt[(kk + 4) * 136 + nb]);
                }
            } else {
#pragma unroll
                for (int ni = 0; ni < 4; ni++) {
                    int nb = wn + ni * 8 + gid;
                    bf[ni][0] = __float_as_uint(Bpt[nb * 20 + kk]);
                    bf[ni][1] = __float_as_uint(Bpt[nb * 20 + kk + 4]);
                }
            }
#pragma unroll
            for (int mi = 0; mi < 2; mi++)
#pragma unroll
                for (int ni = 0; ni < 4; ni++)
                    mma_tf32(c[mi][ni], af[mi], bf[ni]);
        }
    }
#undef ISSUE

#pragma unroll
    for (int mi = 0; mi < 2; mi++) {
        int r0 = row0 + wm + mi * 16 + gid;
        int r1 = r0 + 8;
#pragma unroll
        for (int ni = 0; ni < 4; ni++) {
            int cb = col0 + wn + ni * 8 + 2 * tig;
            float bv0 = 0.f, bv1 = 0.f;
            if (bias) {
                if (cb < Np) bv0 = bias[cb];
                if (cb + 1 < Np) bv1 = bias[cb + 1];
            }
            if (r0 < M) {
                if (cb < Np)     Cz[(long)r0 * ldc + cb]     = c[mi][ni][0] + bv0;
                if (cb + 1 < Np) Cz[(long)r0 * ldc + cb + 1] = c[mi][ni][1] + bv1;
            }
            if (r1 < M) {
                if (cb < Np)     Cz[(long)r1 * ldc + cb]     = c[mi][ni][2] + bv0;
                if (cb + 1 < Np) Cz[(long)r1 * ldc + cb + 1] = c[mi][ni][3] + bv1;
            }
        }
    }
}

// ---------------- gemm64 (fp32, kept only for the MV Gram) -------------------
__global__ __launch_bounds__(256) void gemm64_kernel(
    const float* __restrict__ A, const float* __restrict__ Bm,
    const float* __restrict__ bias, float* __restrict__ Cm,
    int M, int Np, int K, int lda, int ldb, int ldc,
    long sA, long sB, long sC, int transB)
{
    const float* Az = A + (long)blockIdx.z * sA;
    const float* Bz = Bm + (long)blockIdx.z * sB;
    float* Cz = Cm + (long)blockIdx.z * sC;
    __shared__ float As[16][64];
    __shared__ float Bs[16][64];
    int tid = threadIdx.x;
    int tx = tid & 15, ty = tid >> 4;
    int row0 = blockIdx.y * 64, col0 = blockIdx.x * 64;
    int lr = tid >> 2, lk = (tid & 3) * 4;
    int bkk = tid >> 4, bn = (tid & 15) * 4;
    const float4 z4 = {0.f, 0.f, 0.f, 0.f};
    float acc[4][4];
#pragma unroll
    for (int i = 0; i < 4; i++)
#pragma unroll
        for (int j = 0; j < 4; j++) acc[i][j] = 0.f;

    for (int k0 = 0; k0 < K; k0 += 16) {
        float4 av = z4, bv = z4;
        if (row0 + lr < M) av = *(const float4*)(Az + (long)(row0 + lr) * lda + k0 + lk);
        if (!transB) {
            if (col0 + bn < Np) bv = *(const float4*)(Bz + (long)(k0 + bkk) * ldb + col0 + bn);
        } else {
            if (col0 + lr < Np) bv = *(const float4*)(Bz + (long)(col0 + lr) * ldb + k0 + lk);
        }
        __syncthreads();
        As[lk+0][lr]=av.x; As[lk+1][lr]=av.y; As[lk+2][lr]=av.z; As[lk+3][lr]=av.w;
        if (!transB) {
            *(float4*)&Bs[bkk][bn] = bv;
        } else {
            Bs[lk+0][lr]=bv.x; Bs[lk+1][lr]=bv.y; Bs[lk+2][lr]=bv.z; Bs[lk+3][lr]=bv.w;
        }
        __syncthreads();
#pragma unroll
        for (int kk = 0; kk < 16; kk++) {
            float4 a4 = *(const float4*)&As[kk][ty * 4];
            float4 b4 = *(const float4*)&Bs[kk][tx * 4];
            float a[4] = {a4.x, a4.y, a4.z, a4.w};
            float b[4] = {b4.x, b4.y, b4.z, b4.w};
#pragma unroll
            for (int i = 0; i < 4; i++)
#pragma unroll
                for (int j = 0; j < 4; j++) acc[i][j] += a[i] * b[j];
        }
    }
#pragma unroll
    for (int i = 0; i < 4; i++) {
        int gr = row0 + ty * 4 + i;
        if (gr >= M) continue;
#pragma unroll
        for (int j = 0; j < 4; j++) {
            int gc = col0 + tx * 4 + j;
            if (gc < Np)
                Cz[(long)gr * ldc + gc] = acc[i][j] + (bias ? bias[gc] : 0.f);
        }
    }
}

// ---------------- weight packers ---------------------------------------------
__global__ void pack_qk_kernel(const float* __restrict__ wq, const float* __restrict__ wk,
                               const float* __restrict__ bq, const float* __restrict__ bk) {
    int idx = blockIdx.x * 256 + threadIdx.x;
    int k = idx >> 9, c = idx & 511;
    g_wqk[idx] = (c < 256) ? wq[k * 256 + c] : wk[k * 256 + c - 256];
    if (idx < 512) g_bqk[idx] = (idx < 256) ? bq[idx] : bk[idx - 256];
}

__global__ void pack_node_kernel(const float* __restrict__ wa, const float* __restrict__ wb,
                                 const float* __restrict__ wu, const float* __restrict__ wv,
                                 float* __restrict__ dst) {
    int idx = blockIdx.x * 256 + threadIdx.x;
    int k = idx >> 11, c = idx & 2047;
    const float* src = (c < 512) ? wa : (c < 1024) ? wb : (c < 1536) ? wu : wv;
    dst[idx] = src[k * 512 + (c & 511)];
}

// ---------------- BN1 ---------------------------------------------------------
__global__ void bn1_stats_kernel() {
    int n = blockIdx.x;
    int cl = threadIdx.x & 63;
    int q = threadIdx.x >> 6;
    int c = blockIdx.y * 64 + cl;
    float s1 = 0.f, s2 = 0.f;
    const float* base = g_h + (long)n * ND * Cch + c;
    for (int r = q; r < ND; r += 4) {
        float v = base[(long)r * Cch];
        s1 += v; s2 += v * v;
    }
    __shared__ float sm1[4][64], sm2[4][64];
    sm1[q][cl] = s1; sm2[q][cl] = s2;
    __syncthreads();
    if (q == 0) {
        s1 = sm1[0][cl] + sm1[1][cl] + sm1[2][cl] + sm1[3][cl];
        s2 = sm2[0][cl] + sm2[1][cl] + sm2[2][cl] + sm2[3][cl];
        float m = s1 / (float)ND;
        float var = s2 / (float)ND - m * m;
        g_bn1m[n * Cch + c] = m;
        g_bn1r[n * Cch + c] = rsqrtf(fmaxf(var, 0.f) + EPS_);
    }
}

__global__ void bn1_apply_kernel() {
    int n = blockIdx.x, b = blockIdx.y;
    int c4 = threadIdx.x;
    float4 m = ((const float4*)(g_bn1m + n * Cch))[c4];
    float4 r = ((const float4*)(g_bn1r + n * Cch))[c4];
    float4* hb = (float4*)(g_h + ((long)(n * Bb + b) * Dd) * Cch) + c4;
    float4 acc = {0.f, 0.f, 0.f, 0.f};
    for (int d = 0; d < Dd; d++) {
        float4 h = hb[(long)d * 128];
        float4 u;
        u.x = fmaxf((h.x - m.x) * r.x, 0.f);
        u.y = fmaxf((h.y - m.y) * r.y, 0.f);
        u.z = fmaxf((h.z - m.z) * r.z, 0.f);
        u.w = fmaxf((h.w - m.w) * r.w, 0.f);
        hb[(long)d * 128] = u;
        acc = f4add(acc, u);
    }
    float inv = 1.f / (float)Dd;
    acc.x *= inv; acc.y *= inv; acc.z *= inv; acc.w *= inv;
    ((float4*)(g_fv + (long)(b * Nn + n) * Cch))[c4] = acc;
}

// ---------------- attn1 softmax ----------------------------------------------
__global__ void softmaxP_kernel() {
    int z = blockIdx.x;
    int tid = threadIdx.x, w = tid >> 5, lane = tid & 31;
    const float* Sb = g_S1 + (long)z * Dd * Dd;
    float* Pb = g_P + (long)z * Dd * 64;
    for (int r = w; r < Dd; r += 8) {
        float v0 = (lane < Dd) ? Sb[r * Dd + lane] * SCALE_ : -1e30f;
        float v1 = (lane + 32 < Dd) ? Sb[r * Dd + lane + 32] * SCALE_ : -1e30f;
        float mx = fmaxf(v0, v1);
#pragma unroll
        for (int o = 16; o; o >>= 1) mx = fmaxf(mx, __shfl_xor_sync(0xffffffffu, mx, o));
        float e0 = (lane < Dd) ? expf(v0 - mx) : 0.f;
        float e1 = (lane + 32 < Dd) ? expf(v1 - mx) : 0.f;
        float s = e0 + e1;
#pragma unroll
        for (int o = 16; o; o >>= 1) s += __shfl_xor_sync(0xffffffffu, s, o);
        float inv = 1.f / s;
        if (lane < Dd) Pb[r * 64 + lane] = e0 * inv;
        Pb[r * 64 + lane + 32] = (lane + 32 < Dd) ? e1 * inv : 0.f;
    }
}

__global__ void bvp_kernel(const float* __restrict__ bv, const float* __restrict__ epw) {
    int c = threadIdx.x;
    float s = 0.f;
    for (int k = 0; k < Cch; k++) s += bv[k] * epw[k * Cch + c];
    g_bvp[c] = s;
}

// ---------------- attn2: per-(b,e) softmax + agg weights + Gram term ----------
__global__ void pg_kernel() {
    int e = blockIdx.x, b = blockIdx.y;
    int i = e / Nn, j = e % Nn;
    __shared__ float P[49][50];
    __shared__ float MVs[Dd * Dd];
    __shared__ float gpart[8];
    int tid = threadIdx.x, w = tid >> 5, lane = tid & 31;
    const float* MVg = g_MV + (long)(b * Nn + i) * (Dd * Dd);
    for (int t = tid; t < Dd * Dd; t += 256) MVs[t] = MVg[t];
    const float* Sb = g_S + (long)b * SQ * SQ + (long)(j * Dd) * SQ + i * Dd;
    for (int r = w; r < Dd; r += 8) {
        float v0 = (lane < Dd) ? Sb[r * SQ + lane] * SCALE_ : -1e30f;
        float v1 = (lane + 32 < Dd) ? Sb[r * SQ + lane + 32] * SCALE_ : -1e30f;
        float mx = fmaxf(v0, v1);
#pragma unroll
        for (int o = 16; o; o >>= 1) mx = fmaxf(mx, __shfl_xor_sync(0xffffffffu, mx, o));
        float e0 = (lane < Dd) ? expf(v0 - mx) : 0.f;
        float e1 = (lane + 32 < Dd) ? expf(v1 - mx) : 0.f;
        float s = e0 + e1;
#pragma unroll
        for (int o = 16; o; o >>= 1) s += __shfl_xor_sync(0xffffffffu, s, o);
        float inv = 1.f / s;
        if (lane < Dd) P[r][lane] = e0 * inv;
        if (lane + 32 < Dd) P[r][lane + 32] = e1 * inv;
    }
    __syncthreads();
    if (tid < Dd) {
        float s = 0.f;
        for (int r = 0; r < Dd; r++) s += P[r][tid];
        g_w[((long)b * Ee + e) * Dd + tid] = s * (1.f / (float)Dd);
    }
    float acc = 0.f;
    for (int r = w; r < Dd; r += 8) {
        float t0 = 0.f, t1 = 0.f;
        for (int bbk = 0; bbk < Dd; bbk++) {
            float p = P[r][bbk];
            t0 += MVs[lane * Dd + bbk] * p;
            if (lane + 32 < Dd) t1 += MVs[(lane + 32) * Dd + bbk] * p;
        }
        acc += P[r][lane] * t0;
        if (lane + 32 < Dd) acc += P[r][lane + 32] * t1;
    }
#pragma unroll
    for (int o = 16; o; o >>= 1) acc += __shfl_xor_sync(0xffffffffu, acc, o);
    if (lane == 0) gpart[w] = acc;
    __syncthreads();
    if (tid == 0) {
        float s = 0.f;
        for (int q = 0; q < 8; q++) s += gpart[q];
        g_gram[b * Ee + e] = s;
    }
}

// zbar = w^T Vp + epb ; stats via Gram identity. grid (12,8)=(i,b), block 512.
__global__ void zbar_stats_kernel(const float* __restrict__ ep_b) {
    int i = blockIdx.x, b = blockIdx.y;
    __shared__ float ws[Nn * Dd];
    __shared__ float red[16][26];
    int tid = threadIdx.x, lane = tid & 31, w = tid >> 5;
    for (int t = tid; t < Nn * Dd; t += 512) {
        int j = t / Dd, d2 = t % Dd;
        ws[t] = g_w[((long)b * Ee + i * Nn + j) * Dd + d2];
    }
    __syncthreads();
    float acc[Nn];
#pragma unroll
    for (int j = 0; j < Nn; j++) acc[j] = 0.f;
    const float* Vb = g_Vp + (long)((b * Nn + i) * Dd) * Cch;
    for (int d2 = 0; d2 < Dd; d2++) {
        float v = Vb[(long)d2 * Cch + tid];
#pragma unroll
        for (int j = 0; j < Nn; j++) acc[j] += ws[j * Dd + d2] * v;
    }
    float eb = ep_b[tid];
    float loc[25];
#pragma unroll
    for (int j = 0; j < Nn; j++) {
        float z = acc[j] + eb;
        g_zbar[((long)b * Ee + i * Nn + j) * Cch + tid] = z;
        loc[j] = z;
        loc[Nn + j] = eb * z;
    }
    loc[24] = eb * eb;
#pragma unroll
    for (int k = 0; k < 25; k++) {
        float v = loc[k];
#pragma unroll
        for (int o = 16; o; o >>= 1) v += __shfl_xor_sync(0xffffffffu, v, o);
        if (lane == 0) red[w][k] = v;
    }
    __syncthreads();
    if (tid < Nn) {
        float S = 0.f, T = 0.f, E = 0.f;
#pragma unroll
        for (int q = 0; q < 16; q++) {
            S += red[q][tid]; T += red[q][Nn + tid]; E += red[q][24];
        }
        int e = i * Nn + tid;
        g_ps1[b * Ee + e] = 49.f * S;
        g_ps2[b * Ee + e] = g_gram[b * Ee + e] + 98.f * T - 49.f * E;
    }
}

// ---------------- cosine adjacency mask --------------------------------------
__global__ void mask_kernel() {
    int b = blockIdx.x;
    __shared__ float sinv[Nn];
    __shared__ float adj[Ee];
    __shared__ float dis[Nn];
    int tid = threadIdx.x, w = tid >> 5, lane = tid & 31;
    for (int n = w; n < Nn; n += 8) {
        const float4* f = (const float4*)(g_fv + (long)(b * Nn + n) * Cch);
        float s = 0.f;
        for (int t = lane; t < 128; t += 32) {
            float4 x = f[t];
            s += x.x * x.x + x.y * x.y + x.z * x.z + x.w * x.w;
        }
#pragma unroll
        for (int o = 16; o; o >>= 1) s += __shfl_xor_sync(0xffffffffu, s, o);
        if (lane == 0) sinv[n] = 1.f / fmaxf(sqrtf(s), 1e-12f);
    }
    __syncthreads();
    for (int e = w; e < Ee; e += 8) {
        int i = e / Nn, jn = e % Nn;
        const float4* fi = (const float4*)(g_fv + (long)(b * Nn + i) * Cch);
        const float4* fj = (const float4*)(g_fv + (long)(b * Nn + jn) * Cch);
        float s = 0.f;
        for (int t = lane; t < 128; t += 32) {
            float4 a = fi[t], c = fj[t];
            s += a.x * c.x + a.y * c.y + a.z * c.z + a.w * c.w;
        }
#pragma unroll
        for (int o = 16; o; o >>= 1) s += __shfl_xor_sync(0xffffffffu, s, o);
        if (lane == 0) adj[e] = s * sinv[i] * sinv[jn];
    }
    __syncthreads();
    if (tid < Nn) {
        float s = 0.f;
        for (int jn = 0; jn < Nn; jn++) s += adj[tid * Nn + jn];
        dis[tid] = rsqrtf(s);
    }
    __syncthreads();
    if (tid < Ee) {
        int i = tid / Nn, jn = tid % Nn;
        g_mask[b * Ee + tid] = adj[tid] * dis[i] * dis[jn];
    }
}

// ---------------- edge BN + mask ---------------------------------------------
__global__ void edge_bn_mask_kernel() {
    int e = blockIdx.x;
    __shared__ float mrs[2];
    int tid = threadIdx.x;
    if (tid == 0) {
        float s1 = 0.f, s2 = 0.f;
        for (int b = 0; b < Bb; b++) { s1 += g_ps1[b * Ee + e]; s2 += g_ps2[b * Ee + e]; }
        float cnt = (float)(Bb * Dd * Cch);
        float m = s1 / cnt;
        float v = s2 / cnt - m * m;
        mrs[0] = m;
        mrs[1] = rsqrtf(fmaxf(v, 0.f) + EPS_);
    }
    __syncthreads();
    float m = mrs[0], r = mrs[1];
    for (int b = 0; b < Bb; b++) {
        float mk = g_mask[b * Ee + e] * r;
        const float4* zb = (const float4*)(g_zbar + (long)(b * Ee + e) * Cch);
        float4* fe = (float4*)(g_fe + (long)(b * Ee + e) * Cch);
        float4 z = zb[tid];
        fe[tid] = make_float4((z.x - m) * mk, (z.y - m) * mk, (z.z - m) * mk, (z.w - m) * mk);
    }
}

// ---------------- GNN layer pieces -------------------------------------------
__global__ void agg_bn_kernel() {
    int e = blockIdx.x;
    int i = e / Nn, jn = e % Nn;
    __shared__ float sm[32];
    int tid = threadIdx.x;
    float4 agg[Bb];
    float s1 = 0.f, s2 = 0.f;
#pragma unroll
    for (int b = 0; b < Bb; b++) {
        float4 va = ((const float4*)(g_xnode + (long)(b * Nn + i) * 2048))[tid];
        float4 vb = ((const float4*)(g_xnode + (long)(b * Nn + jn) * 2048 + 512))[tid];
        float4 vw = ((const float4*)(g_xw + (long)(b * Ee + e) * Cch))[tid];
        float4 v = f4add(f4add(va, vb), vw);
        agg[b] = v;
        s1 += v.x + v.y + v.z + v.w;
        s2 += v.x * v.x + v.y * v.y + v.z * v.z + v.w * v.w;
    }
    s1 = block_reduce_sum(s1, sm);
    s2 = block_reduce_sum(s2, sm);
    float cnt = (float)(Bb * Cch);
    float m = s1 / cnt;
    float r = rsqrtf(fmaxf(s2 / cnt - m * m, 0.f) + EPS_);
#pragma unroll
    for (int b = 0; b < Bb; b++) {
        float4* fe = (float4*)(g_fe + (long)(b * Ee + e) * Cch);
        float4 f = fe[tid], v = agg[b];
        f.x += fmaxf((v.x - m) * r, 0.f);
        f.y += fmaxf((v.y - m) * r, 0.f);
        f.z += fmaxf((v.z - m) * r, 0.f);
        f.w += fmaxf((v.w - m) * r, 0.f);
        fe[tid] = f;
    }
}

__global__ void softmax_msg_kernel() {
    int bi = blockIdx.x;
    int b = bi / Nn, i = bi % Nn;
    int tid = threadIdx.x;
    float4 v[Nn];
    float4 mx = {-1e30f, -1e30f, -1e30f, -1e30f};
#pragma unroll
    for (int jn = 0; jn < Nn; jn++) {
        float4 ed = ((const float4*)(g_fe + (long)(b * Ee + i * Nn + jn) * Cch))[tid];
        float4 s;
        s.x = 1.f / (1.f + expf(-ed.x));
        s.y = 1.f / (1.f + expf(-ed.y));
        s.z = 1.f / (1.f + expf(-ed.z));
        s.w = 1.f / (1.f + expf(-ed.w));
        v[jn] = s;
        mx.x = fmaxf(mx.x, s.x); mx.y = fmaxf(mx.y, s.y);
        mx.z = fmaxf(mx.z, s.z); mx.w = fmaxf(mx.w, s.w);
    }
    float4 sum = {0.f, 0.f, 0.f, 0.f};
#pragma unroll
    for (int jn = 0; jn < Nn; jn++) {
        v[jn].x = expf(v[jn].x - mx.x); v[jn].y = expf(v[jn].y - mx.y);
        v[jn].z = expf(v[jn].z - mx.z); v[jn].w = expf(v[jn].w - mx.w);
        sum = f4add(sum, v[jn]);
    }
    float4 acc = {0.f, 0.f, 0.f, 0.f};
#pragma unroll
    for (int jn = 0; jn < Nn; jn++) {
        float4 u = ((const float4*)(g_xnode + (long)(b * Nn + jn) * 2048 + 1536))[tid];
        acc.x += v[jn].x * u.x; acc.y += v[jn].y * u.y;
        acc.z += v[jn].z * u.z; acc.w += v[jn].w * u.w;
    }
    float4 o;
    o.x = acc.x / (sum.x * (float)Nn); o.y = acc.y / (sum.y * (float)Nn);
    o.z = acc.z / (sum.z * (float)Nn); o.w = acc.w / (sum.w * (float)Nn);
    ((float4*)(g_msg + (long)(b * Nn + i) * Cch))[tid] = o;
}

__global__ void node_bn_kernel() {
    int n = blockIdx.x;
    __shared__ float sm[32];
    int tid = threadIdx.x;
    float4 t[Bb];
    float s1 = 0.f, s2 = 0.f;
#pragma unroll
    for (int b = 0; b < Bb; b++) {
        float4 xu = ((const float4*)(g_xnode + (long)(b * Nn + n) * 2048 + 1024))[tid];
        float4 ms = ((const float4*)(g_msg + (long)(b * Nn + n) * Cch))[tid];
        float4 v = f4add(xu, ms);
        t[b] = v;
        s1 += v.x + v.y + v.z + v.w;
        s2 += v.x * v.x + v.y * v.y + v.z * v.z + v.w * v.w;
    }
    s1 = block_reduce_sum(s1, sm);
    s2 = block_reduce_sum(s2, sm);
    float cnt = (float)(Bb * Cch);
    float m = s1 / cnt;
    float r = rsqrtf(fmaxf(s2 / cnt - m * m, 0.f) + EPS_);
#pragma unroll
    for (int b = 0; b < Bb; b++) {
        float4* fv = (float4*)(g_fv + (long)(b * Nn + n) * Cch);
        float4 f = fv[tid], v = t[b];
        f.x = fmaxf(f.x + (v.x - m) * r, 0.f);
        f.y = fmaxf(f.y + (v.y - m) * r, 0.f);
        f.z = fmaxf(f.z + (v.z - m) * r, 0.f);
        f.w = fmaxf(f.w + (v.w - m) * r, 0.f);
        fv[tid] = f;
    }
}

// ---------------- classifier heads -------------------------------------------
__global__ void cls_kernel(const float* __restrict__ sc_w, float* __restrict__ out) {
    int bn = blockIdx.x;
    int n = bn % Nn;
    __shared__ float sm[32];
    int tid = threadIdx.x;
    float sf = 0.f, ff = 0.f, ss = 0.f;
    for (int c = tid; c < Cch; c += 128) {
        float f = g_fv[(long)bn * Cch + c];
        float s = fmaxf(sc_w[n * Cch + c], 0.f);
        sf += f * s; ff += f * f; ss += s * s;
    }
    sf = block_reduce_sum(sf, sm);
    ff = block_reduce_sum(ff, sm);
    ss = block_reduce_sum(ss, sm);
    if (tid == 0)
        out[bn] = sf / (fmaxf(sqrtf(ff), 1e-12f) * fmaxf(sqrtf(ss), 1e-12f));
}

__global__ void edgefc_kernel(const float* __restrict__ w, const float* __restrict__ bias,
                              float* __restrict__ out) {
    int row = blockIdx.x;
    int tid = threadIdx.x;
    int k = tid >> 5, lane = tid & 31;
    const float* f = g_fe + (long)row * Cch;
    float dot = 0.f;
    for (int c = lane; c < Cch; c += 32) dot += f[c] * w[c * 4 + k];
#pragma unroll
    for (int o = 16; o; o >>= 1) dot += __shfl_xor_sync(0xffffffffu, dot, o);
    if (lane == 0) out[96 + row * 4 + k] = dot + bias[k];
}

// ---------------- host driver -------------------------------------------------
extern "C" void kernel_launch(void* const* d_in, const int* in_sizes, int n_in,
                              void* d_out, int out_size) {
    const float* x      = (const float*)d_in[0];
    const float* Wc     = (const float*)d_in[1];
    const float* fam_wq = (const float*)d_in[3];
    const float* fam_bq = (const float*)d_in[4];
    const float* fam_wk = (const float*)d_in[5];
    const float* fam_wv = (const float*)d_in[7];
    const float* fam_bv = (const float*)d_in[8];
    const float* arm_wq = (const float*)d_in[9];
    const float* arm_bq = (const float*)d_in[10];
    const float* arm_wk = (const float*)d_in[11];
    const float* arm_bk = (const float*)d_in[12];
    const float* arm_wv = (const float*)d_in[13];
    const float* arm_bv = (const float*)d_in[14];
    const float* ep_w   = (const float*)d_in[15];
    const float* ep_b   = (const float*)d_in[16];
    const float* gw[10];
    for (int t = 0; t < 10; t++) gw[t] = (const float*)d_in[17 + t];
    const float* sc_w   = (const float*)d_in[27];
    const float* efc_w  = (const float*)d_in[28];
    const float* efc_b  = (const float*)d_in[29];
    float* out = (float*)d_out;

    float *p_h, *p_q1, *p_k1, *p_v1, *p_S1, *p_P, *p_f1, *p_QK2, *p_Vp, *p_Wvp, *p_bvp;
    float *p_wqk, *p_bqk, *p_S, *p_MV, *p_fv, *p_fe, *p_wnA, *p_wnB, *p_xnode, *p_xw;
    cudaGetSymbolAddress((void**)&p_h, g_h);
    cudaGetSymbolAddress((void**)&p_q1, g_q1);
    cudaGetSymbolAddress((void**)&p_k1, g_k1);
    cudaGetSymbolAddress((void**)&p_v1, g_v1);
    cudaGetSymbolAddress((void**)&p_S1, g_S1);
    cudaGetSymbolAddress((void**)&p_P, g_P);
    cudaGetSymbolAddress((void**)&p_f1, g_feat1);
    cudaGetSymbolAddress((void**)&p_QK2, g_QK2);
    cudaGetSymbolAddress((void**)&p_Vp, g_Vp);
    cudaGetSymbolAddress((void**)&p_Wvp, g_Wvp);
    cudaGetSymbolAddress((void**)&p_bvp, g_bvp);
    cudaGetSymbolAddress((void**)&p_wqk, g_wqk);
    cudaGetSymbolAddress((void**)&p_bqk, g_bqk);
    cudaGetSymbolAddress((void**)&p_S, g_S);
    cudaGetSymbolAddress((void**)&p_MV, g_MV);
    cudaGetSymbolAddress((void**)&p_fv, g_fv);
    cudaGetSymbolAddress((void**)&p_fe, g_fe);
    cudaGetSymbolAddress((void**)&p_wnA, g_wnodeA);
    cudaGetSymbolAddress((void**)&p_wnB, g_wnodeB);
    cudaGetSymbolAddress((void**)&p_xnode, g_xnode);
    cudaGetSymbolAddress((void**)&p_xw, g_xw);

    static cudaStream_t s1 = nullptr, s2 = nullptr;
    static cudaEvent_t evRoot, evPackQK, evK1, evV1, evWvpB, evFv, evFeat1,
                       evMV, evMask, evXn1, evNB1, evXn2;
    if (!s1) {
        cudaStreamCreateWithFlags(&s1, cudaStreamNonBlocking);
        cudaStreamCreateWithFlags(&s2, cudaStreamNonBlocking);
        cudaEventCreateWithFlags(&evRoot, cudaEventDisableTiming);
        cudaEventCreateWithFlags(&evPackQK, cudaEventDisableTiming);
        cudaEventCreateWithFlags(&evK1, cudaEventDisableTiming);
        cudaEventCreateWithFlags(&evV1, cudaEventDisableTiming);
        cudaEventCreateWithFlags(&evWvpB, cudaEventDisableTiming);
        cudaEventCreateWithFlags(&evFv, cudaEventDisableTiming);
        cudaEventCreateWithFlags(&evFeat1, cudaEventDisableTiming);
        cudaEventCreateWithFlags(&evMV, cudaEventDisableTiming);
        cudaEventCreateWithFlags(&evMask, cudaEventDisableTiming);
        cudaEventCreateWithFlags(&evXn1, cudaEventDisableTiming);
        cudaEventCreateWithFlags(&evNB1, cudaEventDisableTiming);
        cudaEventCreateWithFlags(&evXn2, cudaEventDisableTiming);
        cudaFuncSetAttribute(gemm_tc, cudaFuncAttributeMaxDynamicSharedMemorySize, GEMM_SMEM);
    }
    cudaStream_t s0 = 0;

    cudaEventRecord(evRoot, s0);

    // ---- s1: packing + K/V projections of attn1 ----
    cudaStreamWaitEvent(s1, evRoot, 0);
    pack_qk_kernel<<<1024, 256, 0, s1>>>(arm_wq, arm_wk, arm_bq, arm_bk);
    cudaEventRecord(evPackQK, s1);
    gemm_tc<<<dim3(2, 4, 1), 512, GEMM_SMEM, s1>>>(x, fam_wk, nullptr, p_k1, ND, Hh, Cch,
                                           Cch, Hh, Hh, 0, 0, 0, 0, 0, 0, 1, 0);
    cudaEventRecord(evK1, s1);
    gemm_tc<<<dim3(4, 4, 1), 512, GEMM_SMEM, s1>>>(x, fam_wv, fam_bv, p_v1, ND, Cch, Cch,
                                           Cch, Cch, Cch, 0, 0, 0, 0, 0, 0, 1, 0);
    cudaEventRecord(evV1, s1);

    // ---- s2: Wvp/bvp + node-weight packs ----
    cudaStreamWaitEvent(s2, evRoot, 0);
    gemm_tc<<<dim3(4, 4, 1), 512, GEMM_SMEM, s2>>>(arm_wv, ep_w, nullptr, p_Wvp, Cch, Cch, Cch,
                                           Cch, Cch, Cch, 0, 0, 0, 0, 0, 0, 1, 0);
    bvp_kernel<<<1, 512, 0, s2>>>(arm_bv, ep_w);
    cudaEventRecord(evWvpB, s2);
    pack_node_kernel<<<4096, 256, 0, s2>>>(gw[0], gw[1], gw[3], gw[4], p_wnA);
    pack_node_kernel<<<4096, 256, 0, s2>>>(gw[5], gw[6], gw[8], gw[9], p_wnB);

    // ---- s0 main chain: h -> BN1 ----
    gemm_tc<<<dim3(4, 4, 12), 512, GEMM_SMEM, s0>>>(x, Wc, nullptr, p_h, ND, Cch, Cch,
                                            Cch, Cch, Cch,
                                            0, 0, (long)Cch * Cch, 0, (long)ND * Cch, 0, 1, 0);
    bn1_stats_kernel<<<dim3(12, 8), 256, 0, s0>>>();
    bn1_apply_kernel<<<dim3(12, 8), 128, 0, s0>>>();
    cudaEventRecord(evFv, s0);

    // ---- s2: mask + xnode L1 ----
    cudaStreamWaitEvent(s2, evFv, 0);
    mask_kernel<<<Bb, 256, 0, s2>>>();
    cudaEventRecord(evMask, s2);
    gemm_tc<<<dim3(16, 1, 1), 512, GEMM_SMEM, s2>>>(p_fv, p_wnA, nullptr, p_xnode,
                                            Bb * Nn, 2048, Cch, Cch, 2048, 2048,
                                            0, 0, 0, 0, 0, 0, 1, 0);
    cudaEventRecord(evXn1, s2);

    // ---- s0: attn1 ----
    gemm_tc<<<dim3(2, 37, 1), 512, GEMM_SMEM, s0>>>(p_h, fam_wq, fam_bq, p_q1, RQ, Hh, Cch,
                                            Cch, Hh, Hh, 0, 0, 0, 0, 0, 0, 1, 0);
    cudaStreamWaitEvent(s0, evK1, 0);
    gemm_tc<<<dim3(1, 1, 96), 512, GEMM_SMEM, s0>>>(p_q1, p_k1, nullptr, p_S1, Dd, Dd, Hh,
                                            Hh, Hh, Dd,
                                            (long)8 * Dd * Hh, (long)Dd * Hh,
                                            0, (long)Dd * Hh,
                                            (long)8 * Dd * Dd, (long)Dd * Dd, 8, 1);
    softmaxP_kernel<<<96, 256, 0, s0>>>();
    cudaStreamWaitEvent(s0, evV1, 0);
    gemm_tc<<<dim3(4, 1, 96), 512, GEMM_SMEM, s0>>>(p_P, p_v1, nullptr, p_f1, Dd, Cch, 64,
                                            64, Cch, Cch,
                                            (long)8 * Dd * 64, (long)Dd * 64,
                                            0, (long)Dd * Cch,
                                            (long)Dd * Cch, (long)Nn * Dd * Cch, 8, 0);
    cudaEventRecord(evFeat1, s0);

    // ---- s1: Vp + MV Gram ----
    cudaStreamWaitEvent(s1, evFeat1, 0);
    cudaStreamWaitEvent(s1, evWvpB, 0);
    gemm_tc<<<dim3(4, 37, 1), 512, GEMM_SMEM, s1>>>(p_f1, p_Wvp, p_bvp, p_Vp, RQ, Cch, Cch,
                                            Cch, Cch, Cch, 0, 0, 0, 0, 0, 0, 1, 0);
    gemm64_kernel<<<dim3(1, 1, 96), 256, 0, s1>>>(p_Vp, p_Vp, nullptr, p_MV,
                                                  Dd, Dd, Cch, Cch, Cch, Dd,
                                                  (long)Dd * Cch, (long)Dd * Cch, (long)Dd * Dd, 1);
    cudaEventRecord(evMV, s1);

    // ---- s0: QK2 -> S -> pg -> zbar -> edge ----
    cudaStreamWaitEvent(s0, evPackQK, 0);
    gemm_tc<<<dim3(4, 37, 1), 512, GEMM_SMEM, s0>>>(p_f1, p_wqk, p_bqk, p_QK2, RQ, Cch, Cch,
                                            Cch, Cch, Cch, 0, 0, 0, 0, 0, 0, 1, 0);
    gemm_tc<<<dim3(5, 5, 8), 512, GEMM_SMEM, s0>>>(p_QK2, p_QK2 + 256, nullptr, p_S, SQ, SQ, Hh,
                                           Cch, Cch, SQ,
                                           (long)SQ * Cch, 0, (long)SQ * Cch, 0,
                                           (long)SQ * SQ, 0, 1, 1);
    cudaStreamWaitEvent(s0, evMV, 0);
    pg_kernel<<<dim3(Ee, Bb), 256, 0, s0>>>();
    zbar_stats_kernel<<<dim3(Nn, Bb), 512, 0, s0>>>(ep_b);
    cudaStreamWaitEvent(s0, evMask, 0);
    edge_bn_mask_kernel<<<Ee, 128, 0, s0>>>();

    // ---- GNN layer 1 ----
    gemm_tc<<<dim3(4, 9, 1), 512, GEMM_SMEM, s0>>>(p_fe, gw[2], nullptr, p_xw,
                                           Bb * Ee, Cch, Cch, Cch, Cch, Cch,
                                           0, 0, 0, 0, 0, 0, 1, 0);
    cudaStreamWaitEvent(s0, evXn1, 0);
    agg_bn_kernel<<<Ee, 128, 0, s0>>>();
    softmax_msg_kernel<<<Bb * Nn, 128, 0, s0>>>();
    node_bn_kernel<<<Nn, 128, 0, s0>>>();
    cudaEventRecord(evNB1, s0);

    // ---- GNN layer 2 ----
    cudaStreamWaitEvent(s1, evNB1, 0);
    gemm_tc<<<dim3(16, 1, 1), 512, GEMM_SMEM, s1>>>(p_fv, p_wnB, nullptr, p_xnode,
                                            Bb * Nn, 2048, Cch, Cch, 2048, 2048,
                                            0, 0, 0, 0, 0, 0, 1, 0);
    cudaEventRecord(evXn2, s1);
    gemm_tc<<<dim3(4, 9, 1), 512, GEMM_SMEM, s0>>>(p_fe, gw[7], nullptr, p_xw,
                                           Bb * Ee, Cch, Cch, Cch, Cch, Cch,
                                           0, 0, 0, 0, 0, 0, 1, 0);
    cudaStreamWaitEvent(s0, evXn2, 0);
    agg_bn_kernel<<<Ee, 128, 0, s0>>>();
    softmax_msg_kernel<<<Bb * Nn, 128, 0, s0>>>();
    node_bn_kernel<<<Nn, 128, 0, s0>>>();

    cls_kernel<<<Bb * Nn, 128, 0, s0>>>(sc_w, out);
    edgefc_kernel<<<Bb * Ee, 128, 0, s0>>>(efc_w, efc_b, out);
}

// round 17
// speedup vs baseline: 1.1146x; 1.1146x over previous
#include <cuda_runtime.h>
#include <math.h>
#include <stdint.h>

// Problem constants
#define Bb   8
#define Dd   49
#define Cch  512
#define Nn   12
#define Hh   256          // C/2
#define Ee   144          // N*N
#define ND   392          // B*D
#define RQ   4704         // N*B*D
#define SQ   588          // N*D (rows per batch in attn2)
#define SCALE_ 0.0625f    // (C/2)^-0.5
#define EPS_  1e-5f

#define GEMM_SMEM 81920   // 4 stages * (A 10240B + B 10240B), BK=16

// ---------------- static device scratch (zero-initialized at load) ----------
__device__ float g_h[RQ * Cch];
__device__ float g_q1[RQ * Hh];
__device__ float g_k1[ND * Hh];
__device__ float g_v1[(ND + 16) * Cch];  // padded rows stay 0 (zero-init)
__device__ float g_S1[96 * Dd * Dd];
__device__ float g_P[96 * Dd * 64];
__device__ float g_feat1[RQ * Cch];      // rows (b*12+n)*49+d  (b-major)
__device__ float g_QK2[RQ * Cch];        // cols 0-255 = Q2, 256-511 = K2
__device__ float g_Vp[RQ * Cch];
__device__ float g_Wvp[Cch * Cch];
__device__ float g_bvp[Cch];
__device__ float g_wqk[Cch * Cch];
__device__ float g_bqk[Cch];
__device__ float g_S[Bb * SQ * SQ];
__device__ float g_MV[Bb * Nn * Dd * Dd];
__device__ float g_w[Bb * Ee * Dd];
__device__ float g_gram[Bb * Ee];
__device__ float g_fv[Bb * Nn * Cch];
__device__ float g_zbar[Bb * Ee * Cch];
__device__ float g_ps1[Bb * Ee];
__device__ float g_ps2[Bb * Ee];
__device__ float g_bn1m[Nn * Cch];
__device__ float g_bn1r[Nn * Cch];
__device__ float g_mask[Bb * Ee];
__device__ float g_fe[Bb * Ee * Cch];
__device__ float g_wnodeA[Cch * 2048];
__device__ float g_wnodeB[Cch * 2048];
__device__ float g_xnode[Bb * Nn * 2048];
__device__ float g_xw[Bb * Ee * Cch];
__device__ float g_msg[Bb * Nn * Cch];

// ---------------- helpers ----------------------------------------------------
__device__ __forceinline__ float block_reduce_sum(float v, float* sm) {
    int lane = threadIdx.x & 31, w = threadIdx.x >> 5;
#pragma unroll
    for (int o = 16; o; o >>= 1) v += __shfl_xor_sync(0xffffffffu, v, o);
    if (lane == 0) sm[w] = v;
    __syncthreads();
    int nw = (blockDim.x + 31) >> 5;
    float r = 0.f;
    if (threadIdx.x < 32) {
        r = (threadIdx.x < nw) ? sm[threadIdx.x] : 0.f;
#pragma unroll
        for (int o = 16; o; o >>= 1) r += __shfl_xor_sync(0xffffffffu, r, o);
        if (threadIdx.x == 0) sm[0] = r;
    }
    __syncthreads();
    r = sm[0];
    __syncthreads();
    return r;
}

__device__ __forceinline__ void mma_tf32(float* c, const uint32_t* a, const uint32_t* b) {
    asm volatile(
        "mma.sync.aligned.m16n8k8.row.col.f32.tf32.tf32.f32 "
        "{%0,%1,%2,%3}, {%4,%5,%6,%7}, {%8,%9}, {%0,%1,%2,%3};"
        : "+f"(c[0]), "+f"(c[1]), "+f"(c[2]), "+f"(c[3])
        : "r"(a[0]), "r"(a[1]), "r"(a[2]), "r"(a[3]), "r"(b[0]), "r"(b[1]));
}

__device__ __forceinline__ void cp16(uint32_t s, const void* g, int sz) {
    asm volatile("cp.async.ca.shared.global [%0], [%1], 16, %2;"
                 :: "r"(s), "l"(g), "r"(sz));
}

__device__ __forceinline__ float4 f4add(float4 a, float4 b) {
    return make_float4(a.x + b.x, a.y + b.y, a.z + b.z, a.w + b.w);
}

// ---------------- gemm_tc: TF32 TC GEMM, 128x128x16, 4-stage cp.async --------
// 512 threads / 16 warps (4x4 warp grid, 32x32 per warp) for latency hiding,
// with __launch_bounds__(512, 2): regs capped at 64/thread so TWO CTAs can
// co-reside per SM (register file 64K) — restores cross-kernel overlap.
// Smem fp32: A[m][k] stride 20, B NN [k][n] stride 136, B NT [n][k] stride 20.
// One commit_group per k-tile; wait_group 2 (depth-3 prefetch); 1 sync/tile.
// MMA consumes raw fp32 bits as tf32 (mantissa truncation) — no cvt in loop.
// OOB rows/cols: predicate src-size=0 with pointer clamped in-bounds.
__global__ __launch_bounds__(512, 2) void gemm_tc(
    const float* __restrict__ A, const float* __restrict__ Bm,
    const float* __restrict__ bias, float* __restrict__ Cm,
    int M, int Np, int K, int lda, int ldb, int ldc,
    long sA1, long sA2, long sB1, long sB2, long sC1, long sC2,
    int zdiv, int transB)
{
    const int S = 4;
    extern __shared__ float smem[];
    float* Asm = smem;              // [S][2560]  A: m*20+k
    float* Bsm = smem + S * 2560;   // [S][2560]  B: NN k*136+n / NT n*20+k

    int z = blockIdx.z;
    int zq = z / zdiv, zr = z % zdiv;
    const float* Az = A + zq * sA1 + (long)zr * sA2;
    const float* Bz = Bm + zq * sB1 + (long)zr * sB2;
    float* Cz = Cm + zq * sC1 + (long)zr * sC2;

    int tid = threadIdx.x;
    int row0 = blockIdx.y * 128, col0 = blockIdx.x * 128;
    int warp = tid >> 5, lane = tid & 31;
    int wm = (warp & 3) * 32, wn = (warp >> 2) * 32;
    int gid = lane >> 2, tig = lane & 3;

    float c[2][4][4];
#pragma unroll
    for (int mi = 0; mi < 2; mi++)
#pragma unroll
        for (int ni = 0; ni < 4; ni++)
#pragma unroll
            for (int q = 0; q < 4; q++) c[mi][ni][q] = 0.f;

    int nt = K >> 4;

#define ISSUE(t)                                                               \
    {                                                                          \
        int k0_ = (t) << 4;                                                    \
        float* Ab_ = Asm + ((t) % S) * 2560;                                   \
        float* Bb_ = Bsm + ((t) % S) * 2560;                                   \
        {                                                                      \
            int row_ = tid >> 2, kq_ = (tid & 3) * 4;                          \
            int gr_ = row0 + row_;                                             \
            int ok_ = (gr_ < M);                                               \
            const float* gp_ = Az + (long)(ok_ ? gr_ : 0) * lda + k0_ + kq_;   \
            uint32_t sa_ = (uint32_t)__cvta_generic_to_shared(                 \
                Ab_ + row_ * 20 + kq_);                                        \
            cp16(sa_, gp_, ok_ ? 16 : 0);                                      \
        }                                                                      \
        if (!transB) {                                                         \
            int kk_ = tid >> 5, n4_ = (tid & 31) * 4;                          \
            int gc_ = col0 + n4_;                                              \
            int ok_ = (gc_ < Np);                                              \
            const float* gp_ = Bz + (long)(k0_ + kk_) * ldb +                  \
                               (ok_ ? gc_ : 0);                                \
            uint32_t sa_ = (uint32_t)__cvta_generic_to_shared(                 \
                Bb_ + kk_ * 136 + n4_);                                        \
            cp16(sa_, gp_, ok_ ? 16 : 0);                                      \
        } else {                                                               \
            int row_ = tid >> 2, kq_ = (tid & 3) * 4;                          \
            int gn_ = col0 + row_;                                             \
            int ok_ = (gn_ < Np);                                              \
            const float* gp_ = Bz + (long)(ok_ ? gn_ : 0) * ldb +              \
                               k0_ + kq_;                                      \
            uint32_t sa_ = (uint32_t)__cvta_generic_to_shared(                 \
                Bb_ + row_ * 20 + kq_);                                        \
            cp16(sa_, gp_, ok_ ? 16 : 0);                                      \
        }                                                                      \
        asm volatile("cp.async.commit_group;");                                \
    }

    // preload S-1 stages (empty commits keep group counts consistent)
#pragma unroll
    for (int pt = 0; pt < S - 1; pt++) {
        if (pt < nt) ISSUE(pt)
        else asm volatile("cp.async.commit_group;");
    }

    for (int t = 0; t < nt; t++) {
        asm volatile("cp.async.wait_group 2;");  // stage t complete
        __syncthreads();                          // visible; prior compute done
        if (t + S - 1 < nt) ISSUE(t + S - 1)
        else asm volatile("cp.async.commit_group;");

        const float* Apt = Asm + (t % S) * 2560;
        const float* Bpt = Bsm + (t % S) * 2560;
#pragma unroll
        for (int k8i = 0; k8i < 2; k8i++) {
            int kk = k8i * 8 + tig;
            uint32_t af[2][4], bf[4][2];
#pragma unroll
            for (int mi = 0; mi < 2; mi++) {
                int mb = wm + mi * 16 + gid;
                af[mi][0] = __float_as_uint(Apt[mb * 20 + kk]);
                af[mi][2] = __float_as_uint(Apt[mb * 20 + kk + 4]);
                af[mi][1] = __float_as_uint(Apt[(mb + 8) * 20 + kk]);
                af[mi][3] = __float_as_uint(Apt[(mb + 8) * 20 + kk + 4]);
            }
            if (!transB) {
#pragma unroll
                for (int ni = 0; ni < 4; ni++) {
                    int nb = wn + ni * 8 + gid;
                    bf[ni][0] = __float_as_uint(Bpt[kk * 136 + nb]);
                    bf[ni][1] = __float_as_uint(Bpt[(kk + 4) * 136 + nb]);
                }
            } else {
#pragma unroll
                for (int ni = 0; ni < 4; ni++) {
                    int nb = wn + ni * 8 + gid;
                    bf[ni][0] = __float_as_uint(Bpt[nb * 20 + kk]);
                    bf[ni][1] = __float_as_uint(Bpt[nb * 20 + kk + 4]);
                }
            }
#pragma unroll
            for (int mi = 0; mi < 2; mi++)
#pragma unroll
                for (int ni = 0; ni < 4; ni++)
                    mma_tf32(c[mi][ni], af[mi], bf[ni]);
        }
    }
#undef ISSUE

#pragma unroll
    for (int mi = 0; mi < 2; mi++) {
        int r0 = row0 + wm + mi * 16 + gid;
        int r1 = r0 + 8;
#pragma unroll
        for (int ni = 0; ni < 4; ni++) {
            int cb = col0 + wn + ni * 8 + 2 * tig;
            float bv0 = 0.f, bv1 = 0.f;
            if (bias) {
                if (cb < Np) bv0 = bias[cb];
                if (cb + 1 < Np) bv1 = bias[cb + 1];
            }
            if (r0 < M) {
                if (cb < Np)     Cz[(long)r0 * ldc + cb]     = c[mi][ni][0] + bv0;
                if (cb + 1 < Np) Cz[(long)r0 * ldc + cb + 1] = c[mi][ni][1] + bv1;
            }
            if (r1 < M) {
                if (cb < Np)     Cz[(long)r1 * ldc + cb]     = c[mi][ni][2] + bv0;
                if (cb + 1 < Np) Cz[(long)r1 * ldc + cb + 1] = c[mi][ni][3] + bv1;
            }
        }
    }
}

// ---------------- gemm64 (fp32, kept only for the MV Gram) -------------------
__global__ __launch_bounds__(256) void gemm64_kernel(
    const float* __restrict__ A, const float* __restrict__ Bm,
    const float* __restrict__ bias, float* __restrict__ Cm,
    int M, int Np, int K, int lda, int ldb, int ldc,
    long sA, long sB, long sC, int transB)
{
    const float* Az = A + (long)blockIdx.z * sA;
    const float* Bz = Bm + (long)blockIdx.z * sB;
    float* Cz = Cm + (long)blockIdx.z * sC;
    __shared__ float As[16][64];
    __shared__ float Bs[16][64];
    int tid = threadIdx.x;
    int tx = tid & 15, ty = tid >> 4;
    int row0 = blockIdx.y * 64, col0 = blockIdx.x * 64;
    int lr = tid >> 2, lk = (tid & 3) * 4;
    int bkk = tid >> 4, bn = (tid & 15) * 4;
    const float4 z4 = {0.f, 0.f, 0.f, 0.f};
    float acc[4][4];
#pragma unroll
    for (int i = 0; i < 4; i++)
#pragma unroll
        for (int j = 0; j < 4; j++) acc[i][j] = 0.f;

    for (int k0 = 0; k0 < K; k0 += 16) {
        float4 av = z4, bv = z4;
        if (row0 + lr < M) av = *(const float4*)(Az + (long)(row0 + lr) * lda + k0 + lk);
        if (!transB) {
            if (col0 + bn < Np) bv = *(const float4*)(Bz + (long)(k0 + bkk) * ldb + col0 + bn);
        } else {
            if (col0 + lr < Np) bv = *(const float4*)(Bz + (long)(col0 + lr) * ldb + k0 + lk);
        }
        __syncthreads();
        As[lk+0][lr]=av.x; As[lk+1][lr]=av.y; As[lk+2][lr]=av.z; As[lk+3][lr]=av.w;
        if (!transB) {
            *(float4*)&Bs[bkk][bn] = bv;
        } else {
            Bs[lk+0][lr]=bv.x; Bs[lk+1][lr]=bv.y; Bs[lk+2][lr]=bv.z; Bs[lk+3][lr]=bv.w;
        }
        __syncthreads();
#pragma unroll
        for (int kk = 0; kk < 16; kk++) {
            float4 a4 = *(const float4*)&As[kk][ty * 4];
            float4 b4 = *(const float4*)&Bs[kk][tx * 4];
            float a[4] = {a4.x, a4.y, a4.z, a4.w};
            float b[4] = {b4.x, b4.y, b4.z, b4.w};
#pragma unroll
            for (int i = 0; i < 4; i++)
#pragma unroll
                for (int j = 0; j < 4; j++) acc[i][j] += a[i] * b[j];
        }
    }
#pragma unroll
    for (int i = 0; i < 4; i++) {
        int gr = row0 + ty * 4 + i;
        if (gr >= M) continue;
#pragma unroll
        for (int j = 0; j < 4; j++) {
            int gc = col0 + tx * 4 + j;
            if (gc < Np)
                Cz[(long)gr * ldc + gc] = acc[i][j] + (bias ? bias[gc] : 0.f);
        }
    }
}

// ---------------- weight packers ---------------------------------------------
__global__ void pack_qk_kernel(const float* __restrict__ wq, const float* __restrict__ wk,
                               const float* __restrict__ bq, const float* __restrict__ bk) {
    int idx = blockIdx.x * 256 + threadIdx.x;
    int k = idx >> 9, c = idx & 511;
    g_wqk[idx] = (c < 256) ? wq[k * 256 + c] : wk[k * 256 + c - 256];
    if (idx < 512) g_bqk[idx] = (idx < 256) ? bq[idx] : bk[idx - 256];
}

__global__ void pack_node_kernel(const float* __restrict__ wa, const float* __restrict__ wb,
                                 const float* __restrict__ wu, const float* __restrict__ wv,
                                 float* __restrict__ dst) {
    int idx = blockIdx.x * 256 + threadIdx.x;
    int k = idx >> 11, c = idx & 2047;
    const float* src = (c < 512) ? wa : (c < 1024) ? wb : (c < 1536) ? wu : wv;
    dst[idx] = src[k * 512 + (c & 511)];
}

// ---------------- BN1 ---------------------------------------------------------
__global__ void bn1_stats_kernel() {
    int n = blockIdx.x;
    int cl = threadIdx.x & 63;
    int q = threadIdx.x >> 6;
    int c = blockIdx.y * 64 + cl;
    float s1 = 0.f, s2 = 0.f;
    const float* base = g_h + (long)n * ND * Cch + c;
    for (int r = q; r < ND; r += 4) {
        float v = base[(long)r * Cch];
        s1 += v; s2 += v * v;
    }
    __shared__ float sm1[4][64], sm2[4][64];
    sm1[q][cl] = s1; sm2[q][cl] = s2;
    __syncthreads();
    if (q == 0) {
        s1 = sm1[0][cl] + sm1[1][cl] + sm1[2][cl] + sm1[3][cl];
        s2 = sm2[0][cl] + sm2[1][cl] + sm2[2][cl] + sm2[3][cl];
        float m = s1 / (float)ND;
        float var = s2 / (float)ND - m * m;
        g_bn1m[n * Cch + c] = m;
        g_bn1r[n * Cch + c] = rsqrtf(fmaxf(var, 0.f) + EPS_);
    }
}

__global__ void bn1_apply_kernel() {
    int n = blockIdx.x, b = blockIdx.y;
    int c4 = threadIdx.x;
    float4 m = ((const float4*)(g_bn1m + n * Cch))[c4];
    float4 r = ((const float4*)(g_bn1r + n * Cch))[c4];
    float4* hb = (float4*)(g_h + ((long)(n * Bb + b) * Dd) * Cch) + c4;
    float4 acc = {0.f, 0.f, 0.f, 0.f};
    for (int d = 0; d < Dd; d++) {
        float4 h = hb[(long)d * 128];
        float4 u;
        u.x = fmaxf((h.x - m.x) * r.x, 0.f);
        u.y = fmaxf((h.y - m.y) * r.y, 0.f);
        u.z = fmaxf((h.z - m.z) * r.z, 0.f);
        u.w = fmaxf((h.w - m.w) * r.w, 0.f);
        hb[(long)d * 128] = u;
        acc = f4add(acc, u);
    }
    float inv = 1.f / (float)Dd;
    acc.x *= inv; acc.y *= inv; acc.z *= inv; acc.w *= inv;
    ((float4*)(g_fv + (long)(b * Nn + n) * Cch))[c4] = acc;
}

// ---------------- attn1 softmax ----------------------------------------------
__global__ void softmaxP_kernel() {
    int z = blockIdx.x;
    int tid = threadIdx.x, w = tid >> 5, lane = tid & 31;
    const float* Sb = g_S1 + (long)z * Dd * Dd;
    float* Pb = g_P + (long)z * Dd * 64;
    for (int r = w; r < Dd; r += 8) {
        float v0 = (lane < Dd) ? Sb[r * Dd + lane] * SCALE_ : -1e30f;
        float v1 = (lane + 32 < Dd) ? Sb[r * Dd + lane + 32] * SCALE_ : -1e30f;
        float mx = fmaxf(v0, v1);
#pragma unroll
        for (int o = 16; o; o >>= 1) mx = fmaxf(mx, __shfl_xor_sync(0xffffffffu, mx, o));
        float e0 = (lane < Dd) ? expf(v0 - mx) : 0.f;
        float e1 = (lane + 32 < Dd) ? expf(v1 - mx) : 0.f;
        float s = e0 + e1;
#pragma unroll
        for (int o = 16; o; o >>= 1) s += __shfl_xor_sync(0xffffffffu, s, o);
        float inv = 1.f / s;
        if (lane < Dd) Pb[r * 64 + lane] = e0 * inv;
        Pb[r * 64 + lane + 32] = (lane + 32 < Dd) ? e1 * inv : 0.f;
    }
}

__global__ void bvp_kernel(const float* __restrict__ bv, const float* __restrict__ epw) {
    int c = threadIdx.x;
    float s = 0.f;
    for (int k = 0; k < Cch; k++) s += bv[k] * epw[k * Cch + c];
    g_bvp[c] = s;
}

// ---------------- attn2: per-(b,e) softmax + agg weights + Gram term ----------
__global__ void pg_kernel() {
    int e = blockIdx.x, b = blockIdx.y;
    int i = e / Nn, j = e % Nn;
    __shared__ float P[49][50];
    __shared__ float MVs[Dd * Dd];
    __shared__ float gpart[8];
    int tid = threadIdx.x, w = tid >> 5, lane = tid & 31;
    const float* MVg = g_MV + (long)(b * Nn + i) * (Dd * Dd);
    for (int t = tid; t < Dd * Dd; t += 256) MVs[t] = MVg[t];
    const float* Sb = g_S + (long)b * SQ * SQ + (long)(j * Dd) * SQ + i * Dd;
    for (int r = w; r < Dd; r += 8) {
        float v0 = (lane < Dd) ? Sb[r * SQ + lane] * SCALE_ : -1e30f;
        float v1 = (lane + 32 < Dd) ? Sb[r * SQ + lane + 32] * SCALE_ : -1e30f;
        float mx = fmaxf(v0, v1);
#pragma unroll
        for (int o = 16; o; o >>= 1) mx = fmaxf(mx, __shfl_xor_sync(0xffffffffu, mx, o));
        float e0 = (lane < Dd) ? expf(v0 - mx) : 0.f;
        float e1 = (lane + 32 < Dd) ? expf(v1 - mx) : 0.f;
        float s = e0 + e1;
#pragma unroll
        for (int o = 16; o; o >>= 1) s += __shfl_xor_sync(0xffffffffu, s, o);
        float inv = 1.f / s;
        if (lane < Dd) P[r][lane] = e0 * inv;
        if (lane + 32 < Dd) P[r][lane + 32] = e1 * inv;
    }
    __syncthreads();
    if (tid < Dd) {
        float s = 0.f;
        for (int r = 0; r < Dd; r++) s += P[r][tid];
        g_w[((long)b * Ee + e) * Dd + tid] = s * (1.f / (float)Dd);
    }
    float acc = 0.f;
    for (int r = w; r < Dd; r += 8) {
        float t0 = 0.f, t1 = 0.f;
        for (int bbk = 0; bbk < Dd; bbk++) {
            float p = P[r][bbk];
            t0 += MVs[lane * Dd + bbk] * p;
            if (lane + 32 < Dd) t1 += MVs[(lane + 32) * Dd + bbk] * p;
        }
        acc += P[r][lane] * t0;
        if (lane + 32 < Dd) acc += P[r][lane + 32] * t1;
    }
#pragma unroll
    for (int o = 16; o; o >>= 1) acc += __shfl_xor_sync(0xffffffffu, acc, o);
    if (lane == 0) gpart[w] = acc;
    __syncthreads();
    if (tid == 0) {
        float s = 0.f;
        for (int q = 0; q < 8; q++) s += gpart[q];
        g_gram[b * Ee + e] = s;
    }
}

// zbar = w^T Vp + epb ; stats via Gram identity. grid (12,8)=(i,b), block 512.
__global__ void zbar_stats_kernel(const float* __restrict__ ep_b) {
    int i = blockIdx.x, b = blockIdx.y;
    __shared__ float ws[Nn * Dd];
    __shared__ float red[16][26];
    int tid = threadIdx.x, lane = tid & 31, w = tid >> 5;
    for (int t = tid; t < Nn * Dd; t += 512) {
        int j = t / Dd, d2 = t % Dd;
        ws[t] = g_w[((long)b * Ee + i * Nn + j) * Dd + d2];
    }
    __syncthreads();
    float acc[Nn];
#pragma unroll
    for (int j = 0; j < Nn; j++) acc[j] = 0.f;
    const float* Vb = g_Vp + (long)((b * Nn + i) * Dd) * Cch;
    for (int d2 = 0; d2 < Dd; d2++) {
        float v = Vb[(long)d2 * Cch + tid];
#pragma unroll
        for (int j = 0; j < Nn; j++) acc[j] += ws[j * Dd + d2] * v;
    }
    float eb = ep_b[tid];
    float loc[25];
#pragma unroll
    for (int j = 0; j < Nn; j++) {
        float z = acc[j] + eb;
        g_zbar[((long)b * Ee + i * Nn + j) * Cch + tid] = z;
        loc[j] = z;
        loc[Nn + j] = eb * z;
    }
    loc[24] = eb * eb;
#pragma unroll
    for (int k = 0; k < 25; k++) {
        float v = loc[k];
#pragma unroll
        for (int o = 16; o; o >>= 1) v += __shfl_xor_sync(0xffffffffu, v, o);
        if (lane == 0) red[w][k] = v;
    }
    __syncthreads();
    if (tid < Nn) {
        float S = 0.f, T = 0.f, E = 0.f;
#pragma unroll
        for (int q = 0; q < 16; q++) {
            S += red[q][tid]; T += red[q][Nn + tid]; E += red[q][24];
        }
        int e = i * Nn + tid;
        g_ps1[b * Ee + e] = 49.f * S;
        g_ps2[b * Ee + e] = g_gram[b * Ee + e] + 98.f * T - 49.f * E;
    }
}

// ---------------- cosine adjacency mask --------------------------------------
__global__ void mask_kernel() {
    int b = blockIdx.x;
    __shared__ float sinv[Nn];
    __shared__ float adj[Ee];
    __shared__ float dis[Nn];
    int tid = threadIdx.x, w = tid >> 5, lane = tid & 31;
    for (int n = w; n < Nn; n += 8) {
        const float4* f = (const float4*)(g_fv + (long)(b * Nn + n) * Cch);
        float s = 0.f;
        for (int t = lane; t < 128; t += 32) {
            float4 x = f[t];
            s += x.x * x.x + x.y * x.y + x.z * x.z + x.w * x.w;
        }
#pragma unroll
        for (int o = 16; o; o >>= 1) s += __shfl_xor_sync(0xffffffffu, s, o);
        if (lane == 0) sinv[n] = 1.f / fmaxf(sqrtf(s), 1e-12f);
    }
    __syncthreads();
    for (int e = w; e < Ee; e += 8) {
        int i = e / Nn, jn = e % Nn;
        const float4* fi = (const float4*)(g_fv + (long)(b * Nn + i) * Cch);
        const float4* fj = (const float4*)(g_fv + (long)(b * Nn + jn) * Cch);
        float s = 0.f;
        for (int t = lane; t < 128; t += 32) {
            float4 a = fi[t], c = fj[t];
            s += a.x * c.x + a.y * c.y + a.z * c.z + a.w * c.w;
        }
#pragma unroll
        for (int o = 16; o; o >>= 1) s += __shfl_xor_sync(0xffffffffu, s, o);
        if (lane == 0) adj[e] = s * sinv[i] * sinv[jn];
    }
    __syncthreads();
    if (tid < Nn) {
        float s = 0.f;
        for (int jn = 0; jn < Nn; jn++) s += adj[tid * Nn + jn];
        dis[tid] = rsqrtf(s);
    }
    __syncthreads();
    if (tid < Ee) {
        int i = tid / Nn, jn = tid % Nn;
        g_mask[b * Ee + tid] = adj[tid] * dis[i] * dis[jn];
    }
}

// ---------------- edge BN + mask ---------------------------------------------
__global__ void edge_bn_mask_kernel() {
    int e = blockIdx.x;
    __shared__ float mrs[2];
    int tid = threadIdx.x;
    if (tid == 0) {
        float s1 = 0.f, s2 = 0.f;
        for (int b = 0; b < Bb; b++) { s1 += g_ps1[b * Ee + e]; s2 += g_ps2[b * Ee + e]; }
        float cnt = (float)(Bb * Dd * Cch);
        float m = s1 / cnt;
        float v = s2 / cnt - m * m;
        mrs[0] = m;
        mrs[1] = rsqrtf(fmaxf(v, 0.f) + EPS_);
    }
    __syncthreads();
    float m = mrs[0], r = mrs[1];
    for (int b = 0; b < Bb; b++) {
        float mk = g_mask[b * Ee + e] * r;
        const float4* zb = (const float4*)(g_zbar + (long)(b * Ee + e) * Cch);
        float4* fe = (float4*)(g_fe + (long)(b * Ee + e) * Cch);
        float4 z = zb[tid];
        fe[tid] = make_float4((z.x - m) * mk, (z.y - m) * mk, (z.z - m) * mk, (z.w - m) * mk);
    }
}

// ---------------- GNN layer pieces -------------------------------------------
__global__ void agg_bn_kernel() {
    int e = blockIdx.x;
    int i = e / Nn, jn = e % Nn;
    __shared__ float sm[32];
    int tid = threadIdx.x;
    float4 agg[Bb];
    float s1 = 0.f, s2 = 0.f;
#pragma unroll
    for (int b = 0; b < Bb; b++) {
        float4 va = ((const float4*)(g_xnode + (long)(b * Nn + i) * 2048))[tid];
        float4 vb = ((const float4*)(g_xnode + (long)(b * Nn + jn) * 2048 + 512))[tid];
        float4 vw = ((const float4*)(g_xw + (long)(b * Ee + e) * Cch))[tid];
        float4 v = f4add(f4add(va, vb), vw);
        agg[b] = v;
        s1 += v.x + v.y + v.z + v.w;
        s2 += v.x * v.x + v.y * v.y + v.z * v.z + v.w * v.w;
    }
    s1 = block_reduce_sum(s1, sm);
    s2 = block_reduce_sum(s2, sm);
    float cnt = (float)(Bb * Cch);
    float m = s1 / cnt;
    float r = rsqrtf(fmaxf(s2 / cnt - m * m, 0.f) + EPS_);
#pragma unroll
    for (int b = 0; b < Bb; b++) {
        float4* fe = (float4*)(g_fe + (long)(b * Ee + e) * Cch);
        float4 f = fe[tid], v = agg[b];
        f.x += fmaxf((v.x - m) * r, 0.f);
        f.y += fmaxf((v.y - m) * r, 0.f);
        f.z += fmaxf((v.z - m) * r, 0.f);
        f.w += fmaxf((v.w - m) * r, 0.f);
        fe[tid] = f;
    }
}

__global__ void softmax_msg_kernel() {
    int bi = blockIdx.x;
    int b = bi / Nn, i = bi % Nn;
    int tid = threadIdx.x;
    float4 v[Nn];
    float4 mx = {-1e30f, -1e30f, -1e30f, -1e30f};
#pragma unroll
    for (int jn = 0; jn < Nn; jn++) {
        float4 ed = ((const float4*)(g_fe + (long)(b * Ee + i * Nn + jn) * Cch))[tid];
        float4 s;
        s.x = 1.f / (1.f + expf(-ed.x));
        s.y = 1.f / (1.f + expf(-ed.y));
        s.z = 1.f / (1.f + expf(-ed.z));
        s.w = 1.f / (1.f + expf(-ed.w));
        v[jn] = s;
        mx.x = fmaxf(mx.x, s.x); mx.y = fmaxf(mx.y, s.y);
        mx.z = fmaxf(mx.z, s.z); mx.w = fmaxf(mx.w, s.w);
    }
    float4 sum = {0.f, 0.f, 0.f, 0.f};
#pragma unroll
    for (int jn = 0; jn < Nn; jn++) {
        v[jn].x = expf(v[jn].x - mx.x); v[jn].y = expf(v[jn].y - mx.y);
        v[jn].z = expf(v[jn].z - mx.z); v[jn].w = expf(v[jn].w - mx.w);
        sum = f4add(sum, v[jn]);
    }
    float4 acc = {0.f, 0.f, 0.f, 0.f};
#pragma unroll
    for (int jn = 0; jn < Nn; jn++) {
        float4 u = ((const float4*)(g_xnode + (long)(b * Nn + jn) * 2048 + 1536))[tid];
        acc.x += v[jn].x * u.x; acc.y += v[jn].y * u.y;
        acc.z += v[jn].z * u.z; acc.w += v[jn].w * u.w;
    }
    float4 o;
    o.x = acc.x / (sum.x * (float)Nn); o.y = acc.y / (sum.y * (float)Nn);
    o.z = acc.z / (sum.z * (float)Nn); o.w = acc.w / (sum.w * (float)Nn);
    ((float4*)(g_msg + (long)(b * Nn + i) * Cch))[tid] = o;
}

__global__ void node_bn_kernel() {
    int n = blockIdx.x;
    __shared__ float sm[32];
    int tid = threadIdx.x;
    float4 t[Bb];
    float s1 = 0.f, s2 = 0.f;
#pragma unroll
    for (int b = 0; b < Bb; b++) {
        float4 xu = ((const float4*)(g_xnode + (long)(b * Nn + n) * 2048 + 1024))[tid];
        float4 ms = ((const float4*)(g_msg + (long)(b * Nn + n) * Cch))[tid];
        float4 v = f4add(xu, ms);
        t[b] = v;
        s1 += v.x + v.y + v.z + v.w;
        s2 += v.x * v.x + v.y * v.y + v.z * v.z + v.w * v.w;
    }
    s1 = block_reduce_sum(s1, sm);
    s2 = block_reduce_sum(s2, sm);
    float cnt = (float)(Bb * Cch);
    float m = s1 / cnt;
    float r = rsqrtf(fmaxf(s2 / cnt - m * m, 0.f) + EPS_);
#pragma unroll
    for (int b = 0; b < Bb; b++) {
        float4* fv = (float4*)(g_fv + (long)(b * Nn + n) * Cch);
        float4 f = fv[tid], v = t[b];
        f.x = fmaxf(f.x + (v.x - m) * r, 0.f);
        f.y = fmaxf(f.y + (v.y - m) * r, 0.f);
        f.z = fmaxf(f.z + (v.z - m) * r, 0.f);
        f.w = fmaxf(f.w + (v.w - m) * r, 0.f);
        fv[tid] = f;
    }
}

// ---------------- classifier heads -------------------------------------------
__global__ void cls_kernel(const float* __restrict__ sc_w, float* __restrict__ out) {
    int bn = blockIdx.x;
    int n = bn % Nn;
    __shared__ float sm[32];
    int tid = threadIdx.x;
    float sf = 0.f, ff = 0.f, ss = 0.f;
    for (int c = tid; c < Cch; c += 128) {
        float f = g_fv[(long)bn * Cch + c];
        float s = fmaxf(sc_w[n * Cch + c], 0.f);
        sf += f * s; ff += f * f; ss += s * s;
    }
    sf = block_reduce_sum(sf, sm);
    ff = block_reduce_sum(ff, sm);
    ss = block_reduce_sum(ss, sm);
    if (tid == 0)
        out[bn] = sf / (fmaxf(sqrtf(ff), 1e-12f) * fmaxf(sqrtf(ss), 1e-12f));
}

__global__ void edgefc_kernel(const float* __restrict__ w, const float* __restrict__ bias,
                              float* __restrict__ out) {
    int row = blockIdx.x;
    int tid = threadIdx.x;
    int k = tid >> 5, lane = tid & 31;
    const float* f = g_fe + (long)row * Cch;
    float dot = 0.f;
    for (int c = lane; c < Cch; c += 32) dot += f[c] * w[c * 4 + k];
#pragma unroll
    for (int o = 16; o; o >>= 1) dot += __shfl_xor_sync(0xffffffffu, dot, o);
    if (lane == 0) out[96 + row * 4 + k] = dot + bias[k];
}

// ---------------- host driver -------------------------------------------------
extern "C" void kernel_launch(void* const* d_in, const int* in_sizes, int n_in,
                              void* d_out, int out_size) {
    const float* x      = (const float*)d_in[0];
    const float* Wc     = (const float*)d_in[1];
    const float* fam_wq = (const float*)d_in[3];
    const float* fam_bq = (const float*)d_in[4];
    const float* fam_wk = (const float*)d_in[5];
    const float* fam_wv = (const float*)d_in[7];
    const float* fam_bv = (const float*)d_in[8];
    const float* arm_wq = (const float*)d_in[9];
    const float* arm_bq = (const float*)d_in[10];
    const float* arm_wk = (const float*)d_in[11];
    const float* arm_bk = (const float*)d_in[12];
    const float* arm_wv = (const float*)d_in[13];
    const float* arm_bv = (const float*)d_in[14];
    const float* ep_w   = (const float*)d_in[15];
    const float* ep_b   = (const float*)d_in[16];
    const float* gw[10];
    for (int t = 0; t < 10; t++) gw[t] = (const float*)d_in[17 + t];
    const float* sc_w   = (const float*)d_in[27];
    const float* efc_w  = (const float*)d_in[28];
    const float* efc_b  = (const float*)d_in[29];
    float* out = (float*)d_out;

    float *p_h, *p_q1, *p_k1, *p_v1, *p_S1, *p_P, *p_f1, *p_QK2, *p_Vp, *p_Wvp, *p_bvp;
    float *p_wqk, *p_bqk, *p_S, *p_MV, *p_fv, *p_fe, *p_wnA, *p_wnB, *p_xnode, *p_xw;
    cudaGetSymbolAddress((void**)&p_h, g_h);
    cudaGetSymbolAddress((void**)&p_q1, g_q1);
    cudaGetSymbolAddress((void**)&p_k1, g_k1);
    cudaGetSymbolAddress((void**)&p_v1, g_v1);
    cudaGetSymbolAddress((void**)&p_S1, g_S1);
    cudaGetSymbolAddress((void**)&p_P, g_P);
    cudaGetSymbolAddress((void**)&p_f1, g_feat1);
    cudaGetSymbolAddress((void**)&p_QK2, g_QK2);
    cudaGetSymbolAddress((void**)&p_Vp, g_Vp);
    cudaGetSymbolAddress((void**)&p_Wvp, g_Wvp);
    cudaGetSymbolAddress((void**)&p_bvp, g_bvp);
    cudaGetSymbolAddress((void**)&p_wqk, g_wqk);
    cudaGetSymbolAddress((void**)&p_bqk, g_bqk);
    cudaGetSymbolAddress((void**)&p_S, g_S);
    cudaGetSymbolAddress((void**)&p_MV, g_MV);
    cudaGetSymbolAddress((void**)&p_fv, g_fv);
    cudaGetSymbolAddress((void**)&p_fe, g_fe);
    cudaGetSymbolAddress((void**)&p_wnA, g_wnodeA);
    cudaGetSymbolAddress((void**)&p_wnB, g_wnodeB);
    cudaGetSymbolAddress((void**)&p_xnode, g_xnode);
    cudaGetSymbolAddress((void**)&p_xw, g_xw);

    static cudaStream_t s1 = nullptr, s2 = nullptr;
    static cudaEvent_t evRoot, evPackQK, evK1, evV1, evWvpB, evFv, evFeat1,
                       evMV, evMask, evXn1, evNB1, evXn2;
    if (!s1) {
        cudaStreamCreateWithFlags(&s1, cudaStreamNonBlocking);
        cudaStreamCreateWithFlags(&s2, cudaStreamNonBlocking);
        cudaEventCreateWithFlags(&evRoot, cudaEventDisableTiming);
        cudaEventCreateWithFlags(&evPackQK, cudaEventDisableTiming);
        cudaEventCreateWithFlags(&evK1, cudaEventDisableTiming);
        cudaEventCreateWithFlags(&evV1, cudaEventDisableTiming);
        cudaEventCreateWithFlags(&evWvpB, cudaEventDisableTiming);
        cudaEventCreateWithFlags(&evFv, cudaEventDisableTiming);
        cudaEventCreateWithFlags(&evFeat1, cudaEventDisableTiming);
        cudaEventCreateWithFlags(&evMV, cudaEventDisableTiming);
        cudaEventCreateWithFlags(&evMask, cudaEventDisableTiming);
        cudaEventCreateWithFlags(&evXn1, cudaEventDisableTiming);
        cudaEventCreateWithFlags(&evNB1, cudaEventDisableTiming);
        cudaEventCreateWithFlags(&evXn2, cudaEventDisableTiming);
        cudaFuncSetAttribute(gemm_tc, cudaFuncAttributeMaxDynamicSharedMemorySize, GEMM_SMEM);
    }
    cudaStream_t s0 = 0;

    cudaEventRecord(evRoot, s0);

    // ---- s1: packing + K/V projections of attn1 ----
    cudaStreamWaitEvent(s1, evRoot, 0);
    pack_qk_kernel<<<1024, 256, 0, s1>>>(arm_wq, arm_wk, arm_bq, arm_bk);
    cudaEventRecord(evPackQK, s1);
    gemm_tc<<<dim3(2, 4, 1), 512, GEMM_SMEM, s1>>>(x, fam_wk, nullptr, p_k1, ND, Hh, Cch,
                                           Cch, Hh, Hh, 0, 0, 0, 0, 0, 0, 1, 0);
    cudaEventRecord(evK1, s1);
    gemm_tc<<<dim3(4, 4, 1), 512, GEMM_SMEM, s1>>>(x, fam_wv, fam_bv, p_v1, ND, Cch, Cch,
                                           Cch, Cch, Cch, 0, 0, 0, 0, 0, 0, 1, 0);
    cudaEventRecord(evV1, s1);

    // ---- s2: Wvp/bvp + node-weight packs ----
    cudaStreamWaitEvent(s2, evRoot, 0);
    gemm_tc<<<dim3(4, 4, 1), 512, GEMM_SMEM, s2>>>(arm_wv, ep_w, nullptr, p_Wvp, Cch, Cch, Cch,
                                           Cch, Cch, Cch, 0, 0, 0, 0, 0, 0, 1, 0);
    bvp_kernel<<<1, 512, 0, s2>>>(arm_bv, ep_w);
    cudaEventRecord(evWvpB, s2);
    pack_node_kernel<<<4096, 256, 0, s2>>>(gw[0], gw[1], gw[3], gw[4], p_wnA);
    pack_node_kernel<<<4096, 256, 0, s2>>>(gw[5], gw[6], gw[8], gw[9], p_wnB);

    // ---- s0 main chain: h -> BN1 ----
    gemm_tc<<<dim3(4, 4, 12), 512, GEMM_SMEM, s0>>>(x, Wc, nullptr, p_h, ND, Cch, Cch,
                                            Cch, Cch, Cch,
                                            0, 0, (long)Cch * Cch, 0, (long)ND * Cch, 0, 1, 0);
    bn1_stats_kernel<<<dim3(12, 8), 256, 0, s0>>>();
    bn1_apply_kernel<<<dim3(12, 8), 128, 0, s0>>>();
    cudaEventRecord(evFv, s0);

    // ---- s2: mask + xnode L1 ----
    cudaStreamWaitEvent(s2, evFv, 0);
    mask_kernel<<<Bb, 256, 0, s2>>>();
    cudaEventRecord(evMask, s2);
    gemm_tc<<<dim3(16, 1, 1), 512, GEMM_SMEM, s2>>>(p_fv, p_wnA, nullptr, p_xnode,
                                            Bb * Nn, 2048, Cch, Cch, 2048, 2048,
                                            0, 0, 0, 0, 0, 0, 1, 0);
    cudaEventRecord(evXn1, s2);

    // ---- s0: attn1 ----
    gemm_tc<<<dim3(2, 37, 1), 512, GEMM_SMEM, s0>>>(p_h, fam_wq, fam_bq, p_q1, RQ, Hh, Cch,
                                            Cch, Hh, Hh, 0, 0, 0, 0, 0, 0, 1, 0);
    cudaStreamWaitEvent(s0, evK1, 0);
    gemm_tc<<<dim3(1, 1, 96), 512, GEMM_SMEM, s0>>>(p_q1, p_k1, nullptr, p_S1, Dd, Dd, Hh,
                                            Hh, Hh, Dd,
                                            (long)8 * Dd * Hh, (long)Dd * Hh,
                                            0, (long)Dd * Hh,
                                            (long)8 * Dd * Dd, (long)Dd * Dd, 8, 1);
    softmaxP_kernel<<<96, 256, 0, s0>>>();
    cudaStreamWaitEvent(s0, evV1, 0);
    gemm_tc<<<dim3(4, 1, 96), 512, GEMM_SMEM, s0>>>(p_P, p_v1, nullptr, p_f1, Dd, Cch, 64,
                                            64, Cch, Cch,
                                            (long)8 * Dd * 64, (long)Dd * 64,
                                            0, (long)Dd * Cch,
                                            (long)Dd * Cch, (long)Nn * Dd * Cch, 8, 0);
    cudaEventRecord(evFeat1, s0);

    // ---- s1: Vp + MV Gram ----
    cudaStreamWaitEvent(s1, evFeat1, 0);
    cudaStreamWaitEvent(s1, evWvpB, 0);
    gemm_tc<<<dim3(4, 37, 1), 512, GEMM_SMEM, s1>>>(p_f1, p_Wvp, p_bvp, p_Vp, RQ, Cch, Cch,
                                            Cch, Cch, Cch, 0, 0, 0, 0, 0, 0, 1, 0);
    gemm64_kernel<<<dim3(1, 1, 96), 256, 0, s1>>>(p_Vp, p_Vp, nullptr, p_MV,
                                                  Dd, Dd, Cch, Cch, Cch, Dd,
                                                  (long)Dd * Cch, (long)Dd * Cch, (long)Dd * Dd, 1);
    cudaEventRecord(evMV, s1);

    // ---- s0: QK2 -> S -> pg -> zbar -> edge ----
    cudaStreamWaitEvent(s0, evPackQK, 0);
    gemm_tc<<<dim3(4, 37, 1), 512, GEMM_SMEM, s0>>>(p_f1, p_wqk, p_bqk, p_QK2, RQ, Cch, Cch,
                                            Cch, Cch, Cch, 0, 0, 0, 0, 0, 0, 1, 0);
    gemm_tc<<<dim3(5, 5, 8), 512, GEMM_SMEM, s0>>>(p_QK2, p_QK2 + 256, nullptr, p_S, SQ, SQ, Hh,
                                           Cch, Cch, SQ,
                                           (long)SQ * Cch, 0, (long)SQ * Cch, 0,
                                           (long)SQ * SQ, 0, 1, 1);
    cudaStreamWaitEvent(s0, evMV, 0);
    pg_kernel<<<dim3(Ee, Bb), 256, 0, s0>>>();
    zbar_stats_kernel<<<dim3(Nn, Bb), 512, 0, s0>>>(ep_b);
    cudaStreamWaitEvent(s0, evMask, 0);
    edge_bn_mask_kernel<<<Ee, 128, 0, s0>>>();

    // ---- GNN layer 1 ----
    gemm_tc<<<dim3(4, 9, 1), 512, GEMM_SMEM, s0>>>(p_fe, gw[2], nullptr, p_xw,
                                           Bb * Ee, Cch, Cch, Cch, Cch, Cch,
                                           0, 0, 0, 0, 0, 0, 1, 0);
    cudaStreamWaitEvent(s0, evXn1, 0);
    agg_bn_kernel<<<Ee, 128, 0, s0>>>();
    softmax_msg_kernel<<<Bb * Nn, 128, 0, s0>>>();
    node_bn_kernel<<<Nn, 128, 0, s0>>>();
    cudaEventRecord(evNB1, s0);

    // ---- GNN layer 2 ----
    cudaStreamWaitEvent(s1, evNB1, 0);
    gemm_tc<<<dim3(16, 1, 1), 512, GEMM_SMEM, s1>>>(p_fv, p_wnB, nullptr, p_xnode,
                                            Bb * Nn, 2048, Cch, Cch, 2048, 2048,
                                            0, 0, 0, 0, 0, 0, 1, 0);
    cudaEventRecord(evXn2, s1);
    gemm_tc<<<dim3(4, 9, 1), 512, GEMM_SMEM, s0>>>(p_fe, gw[7], nullptr, p_xw,
                                           Bb * Ee, Cch, Cch, Cch, Cch, Cch,
                                           0, 0, 0, 0, 0, 0, 1, 0);
    cudaStreamWaitEvent(s0, evXn2, 0);
    agg_bn_kernel<<<Ee, 128, 0, s0>>>();
    softmax_msg_kernel<<<Bb * Nn, 128, 0, s0>>>();
    node_bn_kernel<<<Nn, 128, 0, s0>>>();

    cls_kernel<<<Bb * Nn, 128, 0, s0>>>(sc_w, out);
    edgefc_kernel<<<Bb * Ee, 128, 0, s0>>>(efc_w, efc_b, out);
}